// round 1
// baseline (speedup 1.0000x reference)
#include <cuda_runtime.h>
#include <math.h>
#include <math_constants.h>

// Problem constants
#define CB 4
#define CN 1024
#define CD 1024
#define CH 8
#define CHD 128
#define CD4 4096

// Scratch (no allocation allowed -> __device__ globals)
__device__ float g_normed[CB * CN * CD];            // 16 MB
__device__ float g_normed2[CB * CN * CD];           // 16 MB
__device__ float g_x1[CB * CN * CD];                // 16 MB
__device__ float g_scores[(size_t)CB * CH * CN * CN]; // 128 MB
__device__ float g_hbuf[(size_t)CB * CN * CD4];     // 64 MB

// ---------------------------------------------------------------------------
// LayerNorm: one block per row (B*N rows), 256 threads, D=1024 (4 per thread)
// sel==0: src = xext, dst = g_normed ; sel==1: src = g_x1, dst = g_normed2
// ---------------------------------------------------------------------------
__global__ void ln_kernel(const float* __restrict__ xext,
                          const float* __restrict__ lng,
                          const float* __restrict__ lnb,
                          int sel) {
    int row = blockIdx.x;
    const float* src = (sel == 0 ? xext : g_x1) + (size_t)row * CD;
    float* dst = (sel == 0 ? g_normed : g_normed2) + (size_t)row * CD;
    int t = threadIdx.x;

    float v[4];
    float s = 0.f;
#pragma unroll
    for (int i = 0; i < 4; i++) { v[i] = src[t + 256 * i]; s += v[i]; }

    __shared__ float red[8];
#pragma unroll
    for (int o = 16; o; o >>= 1) s += __shfl_xor_sync(0xffffffffu, s, o);
    if ((t & 31) == 0) red[t >> 5] = s;
    __syncthreads();
    float mean = (red[0] + red[1] + red[2] + red[3] +
                  red[4] + red[5] + red[6] + red[7]) * (1.f / CD);
    __syncthreads();

    float s2 = 0.f;
#pragma unroll
    for (int i = 0; i < 4; i++) { float d = v[i] - mean; s2 += d * d; }
#pragma unroll
    for (int o = 16; o; o >>= 1) s2 += __shfl_xor_sync(0xffffffffu, s2, o);
    if ((t & 31) == 0) red[t >> 5] = s2;
    __syncthreads();
    float var = (red[0] + red[1] + red[2] + red[3] +
                 red[4] + red[5] + red[6] + red[7]) * (1.f / CD);
    float rstd = rsqrtf(var + 1e-5f);

#pragma unroll
    for (int i = 0; i < 4; i++) {
        int c = t + 256 * i;
        dst[c] = (v[i] - mean) * rstd * lng[c] + lnb[c];
    }
}

// ---------------------------------------------------------------------------
// Shared 64x64 GEMM core, BK=16, 256 threads, 4x4 microtile per thread.
// A is always [64 rows, K] with leading dim lda (K-contiguous).
// BTRANS=true : B operand is [64 rows, K] K-contiguous (computes A @ B^T)
// BTRANS=false: B operand is [K rows, 64 cols] row-major, ld = ldb
// Caller passes A already offset to its m0 row, B offset to n0 (rows if
// BTRANS, cols if not). Requires K % 16 == 0 and 16B-aligned pointers.
// ---------------------------------------------------------------------------
template <bool BTRANS>
__device__ __forceinline__ void gemm64_core(const float* __restrict__ A, int lda,
                                            const float* __restrict__ Bm, int ldb,
                                            int K, float acc[4][4]) {
    __shared__ float As[16][68];
    __shared__ float Bs[16][68];
    int t = threadIdx.x;
    int tx = t & 15, ty = t >> 4;
    int arow = t >> 2, akp = t & 3;  // 64 rows x 4 float4-packs

    for (int k0 = 0; k0 < K; k0 += 16) {
        float4 av = *(const float4*)(A + (size_t)arow * lda + k0 + akp * 4);
        As[akp * 4 + 0][arow] = av.x;
        As[akp * 4 + 1][arow] = av.y;
        As[akp * 4 + 2][arow] = av.z;
        As[akp * 4 + 3][arow] = av.w;
        if (BTRANS) {
            float4 bv = *(const float4*)(Bm + (size_t)arow * ldb + k0 + akp * 4);
            Bs[akp * 4 + 0][arow] = bv.x;
            Bs[akp * 4 + 1][arow] = bv.y;
            Bs[akp * 4 + 2][arow] = bv.z;
            Bs[akp * 4 + 3][arow] = bv.w;
        } else {
            int brow = t >> 4, bc4 = t & 15;  // 16 k-rows x 16 col-packs
            float4 bv = *(const float4*)(Bm + (size_t)(k0 + brow) * ldb + bc4 * 4);
            *(float4*)&Bs[brow][bc4 * 4] = bv;
        }
        __syncthreads();
#pragma unroll
        for (int kk = 0; kk < 16; kk++) {
            float4 a4 = *(const float4*)&As[kk][ty * 4];
            float4 b4 = *(const float4*)&Bs[kk][tx * 4];
            float ar[4] = {a4.x, a4.y, a4.z, a4.w};
            float br[4] = {b4.x, b4.y, b4.z, b4.w};
#pragma unroll
            for (int i = 0; i < 4; i++)
#pragma unroll
                for (int j = 0; j < 4; j++)
                    acc[i][j] += ar[i] * br[j];
        }
        __syncthreads();
    }
}

// ---------------------------------------------------------------------------
// Scores: per (b,h) S = (Q @ Q^T) * scale, then gate+mask epilogue.
// gate[b,q,k] = sigmoid(stoich[b,q]*gW[k] + gb[k]); masked entries -> -inf
// grid: (16, 16, 32)
// ---------------------------------------------------------------------------
__global__ void scores_kernel(const float* __restrict__ stoich,
                              const int* __restrict__ adj,
                              const float* __restrict__ gW,
                              const float* __restrict__ gb) {
    int bh = blockIdx.z;
    int b = bh / CH, h = bh % CH;
    const float* Q = g_normed + (size_t)b * CN * CD + h * CHD;
    int m0 = blockIdx.y * 64, n0 = blockIdx.x * 64;

    float acc[4][4] = {};
    gemm64_core<true>(Q + (size_t)m0 * CD, CD, Q + (size_t)n0 * CD, CD, CHD, acc);

    int tx = threadIdx.x & 15, ty = threadIdx.x >> 4;
    const float scale = 0.08838834764831845f;  // 1/sqrt(128)
    float* C = g_scores + (size_t)bh * CN * CN;
    const int* adjb = adj + (size_t)b * CN * CN;
#pragma unroll
    for (int i = 0; i < 4; i++) {
        int q = m0 + ty * 4 + i;
        float sq = stoich[b * CN + q];
#pragma unroll
        for (int j = 0; j < 4; j++) {
            int k = n0 + tx * 4 + j;
            float gate = 1.f / (1.f + __expf(-(sq * gW[k] + gb[k])));
            float val = (adjb[(size_t)q * CN + k] > 0)
                            ? acc[i][j] * scale * gate
                            : -CUDART_INF_F;
            C[(size_t)q * CN + k] = val;
        }
    }
}

// ---------------------------------------------------------------------------
// Row softmax over g_scores in place. grid: B*H*N blocks, 256 threads.
// ---------------------------------------------------------------------------
__global__ void softmax_kernel() {
    float* p = g_scores + (size_t)blockIdx.x * CN;
    int t = threadIdx.x;
    float v[4];
    float m = -CUDART_INF_F;
#pragma unroll
    for (int i = 0; i < 4; i++) { v[i] = p[t + 256 * i]; m = fmaxf(m, v[i]); }

    __shared__ float red[8];
#pragma unroll
    for (int o = 16; o; o >>= 1) m = fmaxf(m, __shfl_xor_sync(0xffffffffu, m, o));
    if ((t & 31) == 0) red[t >> 5] = m;
    __syncthreads();
    m = fmaxf(fmaxf(fmaxf(red[0], red[1]), fmaxf(red[2], red[3])),
              fmaxf(fmaxf(red[4], red[5]), fmaxf(red[6], red[7])));
    __syncthreads();

    float s = 0.f;
#pragma unroll
    for (int i = 0; i < 4; i++) { v[i] = __expf(v[i] - m); s += v[i]; }
#pragma unroll
    for (int o = 16; o; o >>= 1) s += __shfl_xor_sync(0xffffffffu, s, o);
    if ((t & 31) == 0) red[t >> 5] = s;
    __syncthreads();
    float tot = red[0] + red[1] + red[2] + red[3] +
                red[4] + red[5] + red[6] + red[7];
    float inv = 1.f / tot;
#pragma unroll
    for (int i = 0; i < 4; i++) p[t + 256 * i] = v[i] * inv;
}

// ---------------------------------------------------------------------------
// Attention out: per (b,h) O = P @ Q  [1024 x 128], fused residual:
// g_x1 = x + O (scattered back to [B,N,D]). grid: (2, 16, 32)
// ---------------------------------------------------------------------------
__global__ void attnout_kernel(const float* __restrict__ x) {
    int bh = blockIdx.z;
    int b = bh / CH, h = bh % CH;
    const float* P = g_scores + (size_t)bh * CN * CN;
    const float* Q = g_normed + (size_t)b * CN * CD + h * CHD;
    int m0 = blockIdx.y * 64, n0 = blockIdx.x * 64;

    float acc[4][4] = {};
    gemm64_core<false>(P + (size_t)m0 * CN, CN, Q + n0, CD, CN, acc);

    int tx = threadIdx.x & 15, ty = threadIdx.x >> 4;
#pragma unroll
    for (int i = 0; i < 4; i++) {
        int q = m0 + ty * 4 + i;
#pragma unroll
        for (int j = 0; j < 4; j++) {
            int dcol = n0 + tx * 4 + j;
            size_t idx = ((size_t)b * CN + q) * CD + h * CHD + dcol;
            g_x1[idx] = x[idx] + acc[i][j];
        }
    }
}

// ---------------------------------------------------------------------------
// MLP1: H = gelu(normed2 @ W1 + b1)  [4096 x 4096], K=1024. grid: (64, 64)
// ---------------------------------------------------------------------------
__global__ void mlp1_kernel(const float* __restrict__ W1,
                            const float* __restrict__ b1) {
    int m0 = blockIdx.y * 64, n0 = blockIdx.x * 64;
    float acc[4][4] = {};
    gemm64_core<false>(g_normed2 + (size_t)m0 * CD, CD, W1 + n0, CD4, CD, acc);

    int tx = threadIdx.x & 15, ty = threadIdx.x >> 4;
#pragma unroll
    for (int i = 0; i < 4; i++) {
        int r = m0 + ty * 4 + i;
#pragma unroll
        for (int j = 0; j < 4; j++) {
            int c = n0 + tx * 4 + j;
            float u = acc[i][j] + b1[c];
            float ge = 0.5f * u * (1.f + erff(u * 0.70710678118654752f));
            g_hbuf[(size_t)r * CD4 + c] = ge;
        }
    }
}

// ---------------------------------------------------------------------------
// MLP2: out = x1 + H @ W2 + b2  [4096 x 1024], K=4096. grid: (16, 64)
// ---------------------------------------------------------------------------
__global__ void mlp2_kernel(const float* __restrict__ W2,
                            const float* __restrict__ b2,
                            float* __restrict__ out) {
    int m0 = blockIdx.y * 64, n0 = blockIdx.x * 64;
    float acc[4][4] = {};
    gemm64_core<false>(g_hbuf + (size_t)m0 * CD4, CD4, W2 + n0, CD, CD4, acc);

    int tx = threadIdx.x & 15, ty = threadIdx.x >> 4;
#pragma unroll
    for (int i = 0; i < 4; i++) {
        int r = m0 + ty * 4 + i;
#pragma unroll
        for (int j = 0; j < 4; j++) {
            int c = n0 + tx * 4 + j;
            size_t idx = (size_t)r * CD + c;
            out[idx] = g_x1[idx] + acc[i][j] + b2[c];
        }
    }
}

// ---------------------------------------------------------------------------
// kernel_launch
// inputs: x, adj_matrix, stoichiometry, ln1_g, ln1_b, ln2_g, ln2_b,
//         W1, b1, W2, b2, gW, gb
// ---------------------------------------------------------------------------
extern "C" void kernel_launch(void* const* d_in, const int* in_sizes, int n_in,
                              void* d_out, int out_size) {
    const float* x      = (const float*)d_in[0];
    const int*   adj    = (const int*)d_in[1];
    const float* stoich = (const float*)d_in[2];
    const float* ln1_g  = (const float*)d_in[3];
    const float* ln1_b  = (const float*)d_in[4];
    const float* ln2_g  = (const float*)d_in[5];
    const float* ln2_b  = (const float*)d_in[6];
    const float* W1     = (const float*)d_in[7];
    const float* b1     = (const float*)d_in[8];
    const float* W2     = (const float*)d_in[9];
    const float* b2     = (const float*)d_in[10];
    const float* gW     = (const float*)d_in[11];
    const float* gb     = (const float*)d_in[12];
    float* out = (float*)d_out;

    // LN1: x -> g_normed
    ln_kernel<<<CB * CN, 256>>>(x, ln1_g, ln1_b, 0);

    // gated+masked scores
    scores_kernel<<<dim3(16, 16, CB * CH), 256>>>(stoich, adj, gW, gb);

    // softmax rows
    softmax_kernel<<<CB * CH * CN, 256>>>();

    // attention output + residual -> g_x1
    attnout_kernel<<<dim3(2, 16, CB * CH), 256>>>(x);

    // LN2: g_x1 -> g_normed2
    ln_kernel<<<CB * CN, 256>>>(x, ln2_g, ln2_b, 1);

    // MLP
    mlp1_kernel<<<dim3(64, 64), 256>>>(W1, b1);
    mlp2_kernel<<<dim3(16, 64), 256>>>(W2, b2, out);
}

// round 5
// speedup vs baseline: 2.0794x; 2.0794x over previous
#include <cuda_runtime.h>
#include <cuda_bf16.h>
#include <math.h>
#include <math_constants.h>
#include <cstdint>

#define CB 4
#define CN 1024
#define CD 1024
#define CH 8
#define CHD 128
#define CD4 4096

typedef __nv_bfloat16 bf16;

// ---------------------------------------------------------------------------
// Device-global scratch — R1's exact buffer set (fp32 everywhere)
// ---------------------------------------------------------------------------
__device__ __align__(1024) float g_normed[CB * CN * CD];              // 16 MB
__device__ __align__(1024) float g_normed2[CB * CN * CD];             // 16 MB
__device__ __align__(1024) float g_x1[CB * CN * CD];                  // 16 MB
__device__ __align__(1024) float g_scores[(size_t)32 * CN * CN];      // 128 MB
__device__ __align__(1024) float g_hbuf[(size_t)CB * CN * CD4];       // 64 MB

// ---------------------------------------------------------------------------
// Helpers
// ---------------------------------------------------------------------------
__device__ __forceinline__ void mma16816(float* d, const uint32_t* a,
                                         const uint32_t* b) {
    asm volatile(
        "mma.sync.aligned.m16n8k16.row.col.f32.bf16.bf16.f32 "
        "{%0,%1,%2,%3}, {%4,%5,%6,%7}, {%8,%9}, {%0,%1,%2,%3};"
        : "+f"(d[0]), "+f"(d[1]), "+f"(d[2]), "+f"(d[3])
        : "r"(a[0]), "r"(a[1]), "r"(a[2]), "r"(a[3]), "r"(b[0]), "r"(b[1]));
}

__device__ __forceinline__ uint32_t pack2(bf16 a, bf16 b) {
    __nv_bfloat162 p = __halves2bfloat162(a, b);  // x = a (low), y = b (high)
    return *reinterpret_cast<uint32_t*>(&p);
}

// split a float4 (4 consecutive k) into hi (2x u32) and lo (2x u32)
__device__ __forceinline__ void split4(float4 v, uint2& hi, uint2& lo) {
    bf16 h0 = __float2bfloat16_rn(v.x), h1 = __float2bfloat16_rn(v.y);
    bf16 h2 = __float2bfloat16_rn(v.z), h3 = __float2bfloat16_rn(v.w);
    hi.x = pack2(h0, h1);
    hi.y = pack2(h2, h3);
    lo.x = pack2(__float2bfloat16_rn(v.x - __bfloat162float(h0)),
                 __float2bfloat16_rn(v.y - __bfloat162float(h1)));
    lo.y = pack2(__float2bfloat16_rn(v.z - __bfloat162float(h2)),
                 __float2bfloat16_rn(v.w - __bfloat162float(h3)));
}

// split+pack two scalars (k, k+1) into one hi reg and one lo reg
__device__ __forceinline__ void splitpack(float a, float b, uint32_t& hi,
                                          uint32_t& lo) {
    bf16 ha = __float2bfloat16_rn(a), hb = __float2bfloat16_rn(b);
    hi = pack2(ha, hb);
    lo = pack2(__float2bfloat16_rn(a - __bfloat162float(ha)),
               __float2bfloat16_rn(b - __bfloat162float(hb)));
}

// smem layout:
//   A region at 0:      128 rows x 144B  ([hi 64B][lo 64B][pad 16B])
//   B region at 18432:  OP0: same 144B layout; else fp32 [32 rows][132 floats]
static constexpr int AROW = 144;
static constexpr int AREG = 128 * AROW;          // 18432
static constexpr int BROWF = 132 * 4;            // 528 bytes
static constexpr int DYN_SMEM = 2 * AREG;        // 36864 (< 48KB default)

// ---------------------------------------------------------------------------
// Unified 128x128-tile split-bf16 mma.sync GEMM over R1's fp32 dataflow.
// OP 0: scores   A=normed  B=normed (n-major) -> g_scores (scale*gate, mask)
// OP 1: attnout  A=scores(P) B=normed [k][n]  -> g_x1 = x + O
// OP 2: mlp1     A=normed2 B=W1 [k][n]        -> g_hbuf = gelu(acc + b1)
// OP 3: mlp2     A=hbuf    B=W2 [k][n]        -> out = x1 + acc + b2
// ---------------------------------------------------------------------------
template <int OP>
__global__ void __launch_bounds__(256)
gemm128(const float* __restrict__ xin, const float* __restrict__ bias,
        const float* __restrict__ stoich, const float* __restrict__ gW,
        const float* __restrict__ gb, const int* __restrict__ adj,
        const float* __restrict__ Wmat, float* __restrict__ outf) {
    extern __shared__ char smem[];
    char* abuf = smem;
    char* bbuf = smem + AREG;

    int t = threadIdx.x, wid = t >> 5, lane = t & 31;
    int mw = wid >> 2, nwp = wid & 3;   // 2 x 4 warp grid (64x32 warp tile)
    int lg = lane >> 2, lt = (lane & 3) * 4;

    int m0, n0, b = 0, h = 0, bh = 0, lda, ldb, K;
    const float *Af, *Bf;
    if (OP == 0) {
        bh = blockIdx.z; b = bh >> 3; h = bh & 7;
        m0 = blockIdx.y * 128; n0 = blockIdx.x * 128;
        lda = ldb = CD; K = CHD;
        Af = g_normed + ((size_t)b * CN + m0) * CD + h * CHD;
        Bf = g_normed + ((size_t)b * CN + n0) * CD + h * CHD;
    } else if (OP == 1) {
        bh = blockIdx.z; b = bh >> 3; h = bh & 7;
        m0 = blockIdx.y * 128; n0 = 0;
        lda = CN; ldb = CD; K = CN;
        Af = g_scores + ((size_t)bh * CN + m0) * CN;
        Bf = g_normed + (size_t)b * CN * CD + h * CHD;
    } else if (OP == 2) {
        m0 = blockIdx.y * 128; n0 = blockIdx.x * 128;
        lda = CD; ldb = CD4; K = CD;
        Af = g_normed2 + (size_t)m0 * CD;
        Bf = Wmat + n0;
    } else {
        m0 = blockIdx.y * 128; n0 = blockIdx.x * 128;
        lda = CD4; ldb = CD; K = CD4;
        Af = g_hbuf + (size_t)m0 * CD4;
        Bf = Wmat + n0;
    }
    constexpr bool BKN = (OP != 0);  // B stored [K rows][N cols] in gmem

    float acc[4][4][4];
#pragma unroll
    for (int i = 0; i < 4; i++)
#pragma unroll
        for (int j = 0; j < 4; j++)
#pragma unroll
            for (int r = 0; r < 4; r++) acc[i][j][r] = 0.f;

    const int C = K / 32;

    // A loader mapping: id = t + 256j -> row = ar + 32j, float4-slot aq
    int ar = t >> 3, aq = t & 7;
    // B fp32 loader mapping: id -> row = br + 8j, float4-slot bq
    int br = t >> 5, bq = t & 31;

    float4 rA[4], rB[4];

#define LDG_STAGE(k0)                                                          \
    do {                                                                       \
        _Pragma("unroll") for (int j = 0; j < 4; j++)                          \
            rA[j] = *(const float4*)(Af + (size_t)(ar + 32 * j) * lda + (k0) + aq * 4); \
        if (!BKN) {                                                            \
            _Pragma("unroll") for (int j = 0; j < 4; j++)                      \
                rB[j] = *(const float4*)(Bf + (size_t)(ar + 32 * j) * ldb + (k0) + aq * 4); \
        } else {                                                               \
            _Pragma("unroll") for (int j = 0; j < 4; j++)                      \
                rB[j] = *(const float4*)(Bf + (size_t)((k0) + br + 8 * j) * ldb + bq * 4); \
        }                                                                      \
    } while (0)

#define STS_STAGE()                                                            \
    do {                                                                       \
        _Pragma("unroll") for (int j = 0; j < 4; j++) {                        \
            uint2 hi, lo;                                                      \
            split4(rA[j], hi, lo);                                             \
            char* p = abuf + (ar + 32 * j) * AROW + aq * 8;                    \
            *(uint2*)p = hi;                                                   \
            *(uint2*)(p + 64) = lo;                                            \
        }                                                                      \
        if (!BKN) {                                                            \
            _Pragma("unroll") for (int j = 0; j < 4; j++) {                    \
                uint2 hi, lo;                                                  \
                split4(rB[j], hi, lo);                                         \
                char* p = bbuf + (ar + 32 * j) * AROW + aq * 8;                \
                *(uint2*)p = hi;                                               \
                *(uint2*)(p + 64) = lo;                                        \
            }                                                                  \
        } else {                                                               \
            _Pragma("unroll") for (int j = 0; j < 4; j++)                      \
                *(float4*)(bbuf + (br + 8 * j) * BROWF + bq * 16) = rB[j];     \
        }                                                                      \
    } while (0)

    LDG_STAGE(0);
    STS_STAGE();
    __syncthreads();

    for (int c = 0; c < C; c++) {
        if (c + 1 < C) LDG_STAGE((c + 1) * 32);

#pragma unroll
        for (int ks = 0; ks < 2; ks++) {
            uint32_t bhf[4][2], blf[4][2];
            if (!BKN) {
#pragma unroll
                for (int nf = 0; nf < 4; nf++) {
                    const char* nb =
                        bbuf + (nwp * 32 + nf * 8 + lg) * AROW + ks * 32 + lt;
                    bhf[nf][0] = *(const uint32_t*)(nb);
                    bhf[nf][1] = *(const uint32_t*)(nb + 16);
                    blf[nf][0] = *(const uint32_t*)(nb + 64);
                    blf[nf][1] = *(const uint32_t*)(nb + 80);
                }
            } else {
                const float* bw = (const float*)bbuf;
                int kb2 = ks * 16 + (lane & 3) * 2;
#pragma unroll
                for (int nf = 0; nf < 4; nf++) {
                    int n = nwp * 32 + nf * 8 + lg;
                    float v0 = bw[(kb2 + 0) * 132 + n];
                    float v1 = bw[(kb2 + 1) * 132 + n];
                    float v8 = bw[(kb2 + 8) * 132 + n];
                    float v9 = bw[(kb2 + 9) * 132 + n];
                    splitpack(v0, v1, bhf[nf][0], blf[nf][0]);
                    splitpack(v8, v9, bhf[nf][1], blf[nf][1]);
                }
            }
#pragma unroll
            for (int mf = 0; mf < 4; mf++) {
                const char* ma =
                    abuf + (mw * 64 + mf * 16 + lg) * AROW + ks * 32 + lt;
                uint32_t ah[4], al[4];
                ah[0] = *(const uint32_t*)(ma);
                ah[1] = *(const uint32_t*)(ma + 8 * AROW);
                ah[2] = *(const uint32_t*)(ma + 16);
                ah[3] = *(const uint32_t*)(ma + 8 * AROW + 16);
                al[0] = *(const uint32_t*)(ma + 64);
                al[1] = *(const uint32_t*)(ma + 8 * AROW + 64);
                al[2] = *(const uint32_t*)(ma + 80);
                al[3] = *(const uint32_t*)(ma + 8 * AROW + 80);
#pragma unroll
                for (int nf = 0; nf < 4; nf++) {
                    mma16816(acc[mf][nf], ah, bhf[nf]);
                    mma16816(acc[mf][nf], ah, blf[nf]);
                    mma16816(acc[mf][nf], al, bhf[nf]);
                }
            }
        }
        __syncthreads();
        if (c + 1 < C) {
            STS_STAGE();
            __syncthreads();
        }
    }

    // ---- fused epilogue (c-frag: rows lg, lg+8; cols (lane&3)*2 + {0,1}) ----
    int c0 = (lane & 3) * 2;
#pragma unroll
    for (int mf = 0; mf < 4; mf++) {
#pragma unroll
        for (int half = 0; half < 2; half++) {
            int gm = m0 + mw * 64 + mf * 16 + lg + half * 8;
            if (OP == 0) {
                float sq = stoich[b * CN + gm];
                size_t srow = ((size_t)bh << 20) + (size_t)gm * CN;
                const int* arow = adj + (size_t)b * CN * CN + (size_t)gm * CN;
#pragma unroll
                for (int nf = 0; nf < 4; nf++) {
#pragma unroll
                    for (int e = 0; e < 2; e++) {
                        int gn = n0 + nwp * 32 + nf * 8 + c0 + e;
                        float v = acc[mf][nf][half * 2 + e];
                        float gate =
                            1.f / (1.f + __expf(-(sq * gW[gn] + gb[gn])));
                        g_scores[srow + gn] =
                            (arow[gn] > 0) ? v * 0.08838834764831845f * gate
                                           : -CUDART_INF_F;
                    }
                }
            } else if (OP == 1) {
                size_t base = ((size_t)b * CN + gm) * CD + h * CHD;
#pragma unroll
                for (int nf = 0; nf < 4; nf++) {
#pragma unroll
                    for (int e = 0; e < 2; e++) {
                        int gn = nwp * 32 + nf * 8 + c0 + e;
                        g_x1[base + gn] =
                            xin[base + gn] + acc[mf][nf][half * 2 + e];
                    }
                }
            } else if (OP == 2) {
                size_t base = (size_t)gm * CD4;
#pragma unroll
                for (int nf = 0; nf < 4; nf++) {
#pragma unroll
                    for (int e = 0; e < 2; e++) {
                        int gn = n0 + nwp * 32 + nf * 8 + c0 + e;
                        float u = acc[mf][nf][half * 2 + e] + bias[gn];
                        g_hbuf[base + gn] =
                            0.5f * u * (1.f + erff(u * 0.7071067811865475f));
                    }
                }
            } else {
                size_t base = (size_t)gm * CD;
#pragma unroll
                for (int nf = 0; nf < 4; nf++) {
#pragma unroll
                    for (int e = 0; e < 2; e++) {
                        int gn = n0 + nwp * 32 + nf * 8 + c0 + e;
                        outf[base + gn] = g_x1[base + gn] +
                                          acc[mf][nf][half * 2 + e] + bias[gn];
                    }
                }
            }
        }
    }
#undef LDG_STAGE
#undef STS_STAGE
}

// ---------------------------------------------------------------------------
// LayerNorm (R1 verbatim): sel==0: x -> g_normed ; sel==1: g_x1 -> g_normed2
// ---------------------------------------------------------------------------
__global__ void ln_kernel(const float* __restrict__ xext,
                          const float* __restrict__ lng,
                          const float* __restrict__ lnb,
                          int sel) {
    int row = blockIdx.x;
    const float* src = (sel == 0 ? xext : g_x1) + (size_t)row * CD;
    float* dst = (sel == 0 ? g_normed : g_normed2) + (size_t)row * CD;
    int t = threadIdx.x;

    float v[4];
    float s = 0.f;
#pragma unroll
    for (int i = 0; i < 4; i++) { v[i] = src[t + 256 * i]; s += v[i]; }

    __shared__ float red[8];
#pragma unroll
    for (int o = 16; o; o >>= 1) s += __shfl_xor_sync(0xffffffffu, s, o);
    if ((t & 31) == 0) red[t >> 5] = s;
    __syncthreads();
    float mean = (red[0] + red[1] + red[2] + red[3] +
                  red[4] + red[5] + red[6] + red[7]) * (1.f / CD);
    __syncthreads();

    float s2 = 0.f;
#pragma unroll
    for (int i = 0; i < 4; i++) { float d = v[i] - mean; s2 += d * d; }
#pragma unroll
    for (int o = 16; o; o >>= 1) s2 += __shfl_xor_sync(0xffffffffu, s2, o);
    if ((t & 31) == 0) red[t >> 5] = s2;
    __syncthreads();
    float var = (red[0] + red[1] + red[2] + red[3] +
                 red[4] + red[5] + red[6] + red[7]) * (1.f / CD);
    float rstd = rsqrtf(var + 1e-5f);

#pragma unroll
    for (int i = 0; i < 4; i++) {
        int c = t + 256 * i;
        dst[c] = (v[i] - mean) * rstd * lng[c] + lnb[c];
    }
}

// ---------------------------------------------------------------------------
// Row softmax over g_scores in place (R1 verbatim). grid B*H*N, 256 thr.
// ---------------------------------------------------------------------------
__global__ void softmax_kernel() {
    float* p = g_scores + (size_t)blockIdx.x * CN;
    int t = threadIdx.x;
    float v[4];
    float m = -CUDART_INF_F;
#pragma unroll
    for (int i = 0; i < 4; i++) { v[i] = p[t + 256 * i]; m = fmaxf(m, v[i]); }

    __shared__ float red[8];
#pragma unroll
    for (int o = 16; o; o >>= 1) m = fmaxf(m, __shfl_xor_sync(0xffffffffu, m, o));
    if ((t & 31) == 0) red[t >> 5] = m;
    __syncthreads();
    m = fmaxf(fmaxf(fmaxf(red[0], red[1]), fmaxf(red[2], red[3])),
              fmaxf(fmaxf(red[4], red[5]), fmaxf(red[6], red[7])));
    __syncthreads();

    float s = 0.f;
#pragma unroll
    for (int i = 0; i < 4; i++) { v[i] = __expf(v[i] - m); s += v[i]; }
#pragma unroll
    for (int o = 16; o; o >>= 1) s += __shfl_xor_sync(0xffffffffu, s, o);
    if ((t & 31) == 0) red[t >> 5] = s;
    __syncthreads();
    float tot = red[0] + red[1] + red[2] + red[3] +
                red[4] + red[5] + red[6] + red[7];
    float inv = 1.f / tot;
#pragma unroll
    for (int i = 0; i < 4; i++) p[t + 256 * i] = v[i] * inv;
}

// ---------------------------------------------------------------------------
// kernel_launch — R1's launch sequence with mma-based GEMMs
// ---------------------------------------------------------------------------
extern "C" void kernel_launch(void* const* d_in, const int* in_sizes, int n_in,
                              void* d_out, int out_size) {
    const float* x      = (const float*)d_in[0];
    const int*   adj    = (const int*)d_in[1];
    const float* stoich = (const float*)d_in[2];
    const float* ln1_g  = (const float*)d_in[3];
    const float* ln1_b  = (const float*)d_in[4];
    const float* ln2_g  = (const float*)d_in[5];
    const float* ln2_b  = (const float*)d_in[6];
    const float* W1     = (const float*)d_in[7];
    const float* b1     = (const float*)d_in[8];
    const float* W2     = (const float*)d_in[9];
    const float* b2     = (const float*)d_in[10];
    const float* gW     = (const float*)d_in[11];
    const float* gb     = (const float*)d_in[12];
    float* out = (float*)d_out;

    // LN1: x -> g_normed
    ln_kernel<<<CB * CN, 256>>>(x, ln1_g, ln1_b, 0);

    // scores = gate-masked (Q Q^T)/sqrt(HD) -> g_scores
    gemm128<0><<<dim3(8, 8, CB * CH), 256, DYN_SMEM>>>(
        nullptr, nullptr, stoich, gW, gb, adj, nullptr, nullptr);

    // softmax rows (in place)
    softmax_kernel<<<CB * CH * CN, 256>>>();

    // attention out + residual -> g_x1
    gemm128<1><<<dim3(1, 8, CB * CH), 256, DYN_SMEM>>>(
        x, nullptr, nullptr, nullptr, nullptr, nullptr, nullptr, nullptr);

    // LN2: g_x1 -> g_normed2
    ln_kernel<<<CB * CN, 256>>>(x, ln2_g, ln2_b, 1);

    // MLP1: gelu(normed2 @ W1 + b1) -> g_hbuf
    gemm128<2><<<dim3(32, 32), 256, DYN_SMEM>>>(
        nullptr, b1, nullptr, nullptr, nullptr, nullptr, W1, nullptr);

    // MLP2: out = x1 + hbuf @ W2 + b2
    gemm128<3><<<dim3(8, 32), 256, DYN_SMEM>>>(
        nullptr, b2, nullptr, nullptr, nullptr, nullptr, W2, out);
}